// round 7
// baseline (speedup 1.0000x reference)
#include <cuda_runtime.h>

// ---------------------------------------------------------------------------
// Single fused kernel.
//
// Phase 1 (warp 0, tid<16): simulate the weight-only circuit on 16 basis
//   columns (embedding phase (-i)^popcount folded in) -> W in shared.
// Phase 2 (tid<24): P[tid] = (1/16) sum_x sgn(popc(x&m1))
//                      sum_j sgn_w(j) (Wre[j][x]Wre[j][y] + Wim[j][x]Wim[j][y]),
//   y = x^m2 — the 24 structurally-nonzero multilinear coefficients
//   (Pauli-propagation sparsity, validated in prior rounds):
//   [0..7]  out0(x0,x1,x3), [8..15] out1(x0,x2,x3),
//   [16..19] out2(x1,x3),   [20..23] out3(x0,x2)
// Phase 3 (all threads): grid-stride streaming evaluation, ~28 FMA + 8 MUFU
//   per sample.
// ---------------------------------------------------------------------------
__global__ __launch_bounds__(256) void qenc_fused_kernel(
    const float* __restrict__ weights,
    const float4* __restrict__ x4,
    float4* __restrict__ out4,
    int n)
{
    __shared__ float shWre[16][16];   // [j][col]
    __shared__ float shWim[16][16];
    __shared__ float sP[24];
    const int tid = threadIdx.x;

    // ---- Phase 1: 16-column circuit simulation (warp 0) ----
    if (tid < 16) {
        const int col = tid;
        float sre[16], sim_[16];
#pragma unroll
        for (int j = 0; j < 16; j++) { sre[j] = (j == col) ? 1.f : 0.f; sim_[j] = 0.f; }

#pragma unroll
        for (int l = 0; l < 2; l++) {
#pragma unroll
            for (int w = 0; w < 4; w++) {
                float th = weights[l * 4 + w] * 0.5f;
                float c, s;
                sincosf(th, &s, &c);
                const int bit = 8 >> w;
#pragma unroll
                for (int j = 0; j < 16; j++) {
                    if (j & bit) continue;
                    const int k = j | bit;
                    float are = sre[j], aim = sim_[j];
                    float bre = sre[k], bim = sim_[k];
                    sre[j] = c * are + s * bim;
                    sim_[j] = c * aim - s * bre;
                    sre[k] = c * bre + s * aim;
                    sim_[k] = c * bim - s * are;
                }
            }
#pragma unroll
            for (int w = 0; w < 4; w++) {
                const int cb = 8 >> w;
                const int tb = 8 >> ((w + 1) & 3);
#pragma unroll
                for (int j = 0; j < 16; j++) {
                    if ((j & cb) && !(j & tb)) {
                        const int k = j | tb;
                        float tre = sre[j], tim = sim_[j];
                        sre[j] = sre[k]; sim_[j] = sim_[k];
                        sre[k] = tre;    sim_[k] = tim;
                    }
                }
            }
        }
        const int pc = __popc(col) & 3;
#pragma unroll
        for (int j = 0; j < 16; j++) {
            float re = sre[j], im = sim_[j];
            float wre, wim;
            if (pc == 0)      { wre = re;   wim = im;  }
            else if (pc == 1) { wre = im;   wim = -re; }
            else if (pc == 2) { wre = -re;  wim = -im; }
            else              { wre = -im;  wim = re;  }
            shWre[j][col] = wre;
            shWim[j][col] = wim;
        }
    }
    __syncthreads();

    // ---- Phase 2: 24 sparse coefficients ----
    if (tid < 24) {
        int w, a, b, c, d;
        if (tid < 8)       { w = 0; a = (tid >> 2) + 1;        b = ((tid >> 1) & 1) + 1; c = 0;                      d = (tid & 1) + 1; }
        else if (tid < 16) { int r = tid - 8;  w = 1; a = (r >> 2) + 1; b = 0; c = ((r >> 1) & 1) + 1;  d = (r & 1) + 1; }
        else if (tid < 20) { int r = tid - 16; w = 2; a = 0;            b = (r >> 1) + 1; c = 0;        d = (r & 1) + 1; }
        else               { int r = tid - 20; w = 3; a = (r >> 1) + 1; b = 0;            c = (r & 1) + 1; d = 0; }

        int m1 = 0, m2 = 0;
        if (a == 1) m1 |= 8; else if (a == 2) m2 |= 8;
        if (b == 1) m1 |= 4; else if (b == 2) m2 |= 4;
        if (c == 1) m1 |= 2; else if (c == 2) m2 |= 2;
        if (d == 1) m1 |= 1; else if (d == 2) m2 |= 1;

        const int bitpos = 3 - w;
        float sum = 0.f;
#pragma unroll
        for (int x = 0; x < 16; x++) {
            const int y = x ^ m2;
            const float sgn1 = (__popc(x & m1) & 1) ? -1.f : 1.f;
            float acc = 0.f;
#pragma unroll
            for (int j = 0; j < 16; j++) {
                const float sgn2 = ((j >> bitpos) & 1) ? -1.f : 1.f;
                acc += sgn2 * (shWre[j][x] * shWre[j][y] + shWim[j][x] * shWim[j][y]);
            }
            sum += sgn1 * acc;
        }
        sP[tid] = sum * 0.0625f;
    }
    __syncthreads();

    // ---- Phase 3: streaming evaluation ----
    float P[24];
#pragma unroll
    for (int k = 0; k < 24; k++) P[k] = sP[k];

    const int stride = gridDim.x * blockDim.x;
    for (int i = blockIdx.x * blockDim.x + tid; i < n; i += stride) {
        const float4 xv = x4[i];
        float c0, s0, c1, s1, c2, s2, c3, s3;
        __sincosf(xv.x, &s0, &c0);
        __sincosf(xv.y, &s1, &c1);
        __sincosf(xv.z, &s2, &c2);
        __sincosf(xv.w, &s3, &c3);

        // out0: wires 0,1,3
        float a1 = fmaf(P[1], s3, P[0] * c3);
        float a2 = fmaf(P[3], s3, P[2] * c3);
        float a3 = fmaf(P[5], s3, P[4] * c3);
        float a4 = fmaf(P[7], s3, P[6] * c3);
        float u1 = fmaf(a2, s1, a1 * c1);
        float u2 = fmaf(a4, s1, a3 * c1);
        const float o0 = fmaf(u2, s0, u1 * c0);

        // out1: wires 0,2,3
        float b1 = fmaf(P[9],  s3, P[8]  * c3);
        float b2 = fmaf(P[11], s3, P[10] * c3);
        float b3 = fmaf(P[13], s3, P[12] * c3);
        float b4 = fmaf(P[15], s3, P[14] * c3);
        float v1 = fmaf(b2, s2, b1 * c2);
        float v2 = fmaf(b4, s2, b3 * c2);
        const float o1 = fmaf(v2, s0, v1 * c0);

        // out2: wires 1,3
        float d1 = fmaf(P[17], s3, P[16] * c3);
        float d2 = fmaf(P[19], s3, P[18] * c3);
        const float o2 = fmaf(d2, s1, d1 * c1);

        // out3: wires 0,2
        float e1 = fmaf(P[21], s2, P[20] * c2);
        float e2 = fmaf(P[23], s2, P[22] * c2);
        const float o3 = fmaf(e2, s0, e1 * c0);

        out4[i] = make_float4(o0, o1, o2, o3);
    }
}

extern "C" void kernel_launch(void* const* d_in, const int* in_sizes, int n_in,
                              void* d_out, int out_size) {
    const float* x = (const float*)d_in[0];        // [B, 4] float32
    const float* weights = (const float*)d_in[1];  // [2, 4] float32
    float* out = (float*)d_out;                    // [B, 4] float32

    const int n = in_sizes[0] / 4;

    // 5 blocks/SM * 148 SMs -> single wave; grid-stride covers all samples.
    int grid = 740;
    const int maxGrid = (n + 255) / 256;
    if (grid > maxGrid) grid = maxGrid;

    qenc_fused_kernel<<<grid, 256>>>(weights, (const float4*)x, (float4*)out, n);
}

// round 8
// speedup vs baseline: 2.9483x; 2.9483x over previous
#include <cuda_runtime.h>

// ---------------------------------------------------------------------------
// Single fused kernel, register-pressure-isolated.
//
// Phase 1 (tid<16): simulate weight-only circuit on 16 basis columns with the
//   statevector IN SHARED MEMORY (keeps hot-loop register budget small);
//   fold embedding phase (-i)^popcount; write W[j][col] to shared.
// Phase 2 (tid<192): 24 sparse coefficients x 8 partials each (2 x-terms per
//   partial), then tid<24 reduces. Coefficients (Pauli-propagation sparsity,
//   validated R6):
//   [0..7]  out0(x0,x1,x3), [8..15] out1(x0,x2,x3),
//   [16..19] out2(x1,x3),   [20..23] out3(x0,x2)
// Phase 3 (all): grid-stride streaming, ~28 FMA + 8 MUFU per sample.
// ---------------------------------------------------------------------------
__global__ void __launch_bounds__(256, 6) qenc_fused_kernel(
    const float* __restrict__ weights,
    const float4* __restrict__ x4,
    float4* __restrict__ out4,
    int n)
{
    __shared__ float svre[16][16];    // [col][j] working statevector
    __shared__ float svim[16][16];
    __shared__ float shWre[16][16];   // [j][col] final W with phase folded
    __shared__ float shWim[16][16];
    __shared__ float sPart[24][8];
    __shared__ float sP[24];
    const int tid = threadIdx.x;

    // ---- Phase 1: circuit simulation in shared memory ----
    if (tid < 16) {
        const int col = tid;
#pragma unroll
        for (int j = 0; j < 16; j++) {
            svre[col][j] = (j == col) ? 1.f : 0.f;
            svim[col][j] = 0.f;
        }

#pragma unroll
        for (int l = 0; l < 2; l++) {
#pragma unroll
            for (int w = 0; w < 4; w++) {
                float th = weights[l * 4 + w] * 0.5f;
                float c, s;
                __sincosf(th, &s, &c);
                const int bit = 8 >> w;
#pragma unroll
                for (int j = 0; j < 16; j++) {
                    if (j & bit) continue;
                    const int k = j | bit;
                    float are = svre[col][j], aim = svim[col][j];
                    float bre = svre[col][k], bim = svim[col][k];
                    svre[col][j] = c * are + s * bim;
                    svim[col][j] = c * aim - s * bre;
                    svre[col][k] = c * bre + s * aim;
                    svim[col][k] = c * bim - s * are;
                }
            }
#pragma unroll
            for (int w = 0; w < 4; w++) {
                const int cb = 8 >> w;
                const int tb = 8 >> ((w + 1) & 3);
#pragma unroll
                for (int j = 0; j < 16; j++) {
                    if ((j & cb) && !(j & tb)) {
                        const int k = j | tb;
                        float tre = svre[col][j], tim = svim[col][j];
                        svre[col][j] = svre[col][k]; svim[col][j] = svim[col][k];
                        svre[col][k] = tre;          svim[col][k] = tim;
                    }
                }
            }
        }
        const int pc = __popc(col) & 3;
#pragma unroll
        for (int j = 0; j < 16; j++) {
            float re = svre[col][j], im = svim[col][j];
            float wre, wim;
            if (pc == 0)      { wre = re;   wim = im;  }
            else if (pc == 1) { wre = im;   wim = -re; }
            else if (pc == 2) { wre = -re;  wim = -im; }
            else              { wre = -im;  wim = re;  }
            shWre[j][col] = wre;
            shWim[j][col] = wim;
        }
    }
    __syncthreads();

    // ---- Phase 2: 24 coefficients, 8-way parallel partials ----
    if (tid < 192) {
        const int coef = tid >> 3;
        const int part = tid & 7;

        int w, a, b, c, d;
        if (coef < 8)       { w = 0; a = (coef >> 2) + 1; b = ((coef >> 1) & 1) + 1; c = 0; d = (coef & 1) + 1; }
        else if (coef < 16) { int r = coef - 8;  w = 1; a = (r >> 2) + 1; b = 0; c = ((r >> 1) & 1) + 1; d = (r & 1) + 1; }
        else if (coef < 20) { int r = coef - 16; w = 2; a = 0; b = (r >> 1) + 1; c = 0; d = (r & 1) + 1; }
        else                { int r = coef - 20; w = 3; a = (r >> 1) + 1; b = 0; c = (r & 1) + 1; d = 0; }

        int m1 = 0, m2 = 0;
        if (a == 1) m1 |= 8; else if (a == 2) m2 |= 8;
        if (b == 1) m1 |= 4; else if (b == 2) m2 |= 4;
        if (c == 1) m1 |= 2; else if (c == 2) m2 |= 2;
        if (d == 1) m1 |= 1; else if (d == 2) m2 |= 1;

        const int bitpos = 3 - w;
        float sum = 0.f;
#pragma unroll
        for (int xo = 0; xo < 2; xo++) {
            const int x = part * 2 + xo;
            const int y = x ^ m2;
            const float sgn1 = (__popc(x & m1) & 1) ? -1.f : 1.f;
            float acc = 0.f;
#pragma unroll
            for (int j = 0; j < 16; j++) {
                const float sgn2 = ((j >> bitpos) & 1) ? -1.f : 1.f;
                acc += sgn2 * (shWre[j][x] * shWre[j][y] + shWim[j][x] * shWim[j][y]);
            }
            sum += sgn1 * acc;
        }
        sPart[coef][part] = sum;
    }
    __syncthreads();

    if (tid < 24) {
        float s = 0.f;
#pragma unroll
        for (int p = 0; p < 8; p++) s += sPart[tid][p];
        sP[tid] = s * 0.0625f;
    }
    __syncthreads();

    // ---- Phase 3: streaming evaluation ----
    float P[24];
#pragma unroll
    for (int k = 0; k < 24; k++) P[k] = sP[k];

    const int stride = gridDim.x * blockDim.x;
    for (int i = blockIdx.x * blockDim.x + tid; i < n; i += stride) {
        const float4 xv = x4[i];
        float c0, s0, c1, s1, c2, s2, c3, s3;
        __sincosf(xv.x, &s0, &c0);
        __sincosf(xv.y, &s1, &c1);
        __sincosf(xv.z, &s2, &c2);
        __sincosf(xv.w, &s3, &c3);

        // out0: wires 0,1,3
        float a1 = fmaf(P[1], s3, P[0] * c3);
        float a2 = fmaf(P[3], s3, P[2] * c3);
        float a3 = fmaf(P[5], s3, P[4] * c3);
        float a4 = fmaf(P[7], s3, P[6] * c3);
        float u1 = fmaf(a2, s1, a1 * c1);
        float u2 = fmaf(a4, s1, a3 * c1);
        const float o0 = fmaf(u2, s0, u1 * c0);

        // out1: wires 0,2,3
        float b1 = fmaf(P[9],  s3, P[8]  * c3);
        float b2 = fmaf(P[11], s3, P[10] * c3);
        float b3 = fmaf(P[13], s3, P[12] * c3);
        float b4 = fmaf(P[15], s3, P[14] * c3);
        float v1 = fmaf(b2, s2, b1 * c2);
        float v2 = fmaf(b4, s2, b3 * c2);
        const float o1 = fmaf(v2, s0, v1 * c0);

        // out2: wires 1,3
        float d1 = fmaf(P[17], s3, P[16] * c3);
        float d2 = fmaf(P[19], s3, P[18] * c3);
        const float o2 = fmaf(d2, s1, d1 * c1);

        // out3: wires 0,2
        float e1 = fmaf(P[21], s2, P[20] * c2);
        float e2 = fmaf(P[23], s2, P[22] * c2);
        const float o3 = fmaf(e2, s0, e1 * c0);

        out4[i] = make_float4(o0, o1, o2, o3);
    }
}

extern "C" void kernel_launch(void* const* d_in, const int* in_sizes, int n_in,
                              void* d_out, int out_size) {
    const float* x = (const float*)d_in[0];        // [B, 4] float32
    const float* weights = (const float*)d_in[1];  // [2, 4] float32
    float* out = (float*)d_out;                    // [B, 4] float32

    const int n = in_sizes[0] / 4;

    // 6 blocks/SM * 148 SMs = one full wave; grid-stride covers the rest.
    int grid = 888;
    const int maxGrid = (n + 255) / 256;
    if (grid > maxGrid) grid = maxGrid;

    qenc_fused_kernel<<<grid, 256>>>(weights, (const float4*)x, (float4*)out, n);
}

// round 9
// speedup vs baseline: 3.3529x; 1.1373x over previous
#include <cuda_runtime.h>

// ---------------------------------------------------------------------------
// Single fused kernel, shuffle-based prep.
//
// Phase 1 (all 256 threads): one amplitude per thread; col = tid>>4 is the
//   basis column, j = tid&15 the amplitude index (low 4 lane bits). RX gates
//   are shfl_xor butterflies, CNOTs are lane permutations. Embedding phase
//   (-i)^popcount(col) folded at the end; W written to shared.
// Phase 2 (tid<192): 24 sparse coefficients x 8 partials (2 x-terms each),
//   then tid<24 reduces. Coefficient set = Pauli-propagation sparsity
//   (validated R6/R8):
//   [0..7]  out0(x0,x1,x3), [8..15] out1(x0,x2,x3),
//   [16..19] out2(x1,x3),   [20..23] out3(x0,x2)
// Phase 3 (all): grid-stride streaming, ~28 FMA + 8 MUFU per sample.
// ---------------------------------------------------------------------------
__global__ void __launch_bounds__(256, 6) qenc_fused_kernel(
    const float* __restrict__ weights,
    const float4* __restrict__ x4,
    float4* __restrict__ out4,
    int n)
{
    __shared__ float shWre[16][16];   // [j][col]
    __shared__ float shWim[16][16];
    __shared__ float sPart[24][8];
    __shared__ float sP[24];
    const int tid = threadIdx.x;
    const unsigned FULL = 0xffffffffu;

    // ---- Phase 1: shuffle-based circuit simulation ----
    {
        const int col = tid >> 4;   // basis column 0..15
        const int j   = tid & 15;   // amplitude index (low 4 lane bits)

        float re = (j == col) ? 1.f : 0.f;
        float im = 0.f;

#pragma unroll
        for (int l = 0; l < 2; l++) {
            // RX(weights[l][w]) on each wire: butterfly over bit (8>>w) of j
#pragma unroll
            for (int w = 0; w < 4; w++) {
                const float th = weights[l * 4 + w] * 0.5f;
                float c, s;
                __sincosf(th, &s, &c);
                const int bit = 8 >> w;
                const float pre = __shfl_xor_sync(FULL, re, bit);
                const float pim = __shfl_xor_sync(FULL, im, bit);
                const float nre = fmaf(c, re,  s * pim);
                const float nim = fmaf(c, im, -s * pre);
                re = nre; im = nim;
            }
            // ring of CNOTs: new_amp[j] = old_amp[(j&cb) ? j^tb : j]
#pragma unroll
            for (int w = 0; w < 4; w++) {
                const int cb = 8 >> w;
                const int tb = 8 >> ((w + 1) & 3);
                const int srcj = (j & cb) ? (j ^ tb) : j;
                const int srclane = (tid & 16) | srcj;   // same col, new j
                re = __shfl_sync(FULL, re, srclane);
                im = __shfl_sync(FULL, im, srclane);
            }
        }

        // fold embedding phase (-i)^popcount(col)
        const int pc = __popc(col) & 3;
        float wre, wim;
        if (pc == 0)      { wre = re;   wim = im;  }
        else if (pc == 1) { wre = im;   wim = -re; }
        else if (pc == 2) { wre = -re;  wim = -im; }
        else              { wre = -im;  wim = re;  }
        shWre[j][col] = wre;
        shWim[j][col] = wim;
    }
    __syncthreads();

    // ---- Phase 2: 24 coefficients, 8-way parallel partials ----
    if (tid < 192) {
        const int coef = tid >> 3;
        const int part = tid & 7;

        int w, a, b, c, d;
        if (coef < 8)       { w = 0; a = (coef >> 2) + 1; b = ((coef >> 1) & 1) + 1; c = 0; d = (coef & 1) + 1; }
        else if (coef < 16) { int r = coef - 8;  w = 1; a = (r >> 2) + 1; b = 0; c = ((r >> 1) & 1) + 1; d = (r & 1) + 1; }
        else if (coef < 20) { int r = coef - 16; w = 2; a = 0; b = (r >> 1) + 1; c = 0; d = (r & 1) + 1; }
        else                { int r = coef - 20; w = 3; a = (r >> 1) + 1; b = 0; c = (r & 1) + 1; d = 0; }

        int m1 = 0, m2 = 0;
        if (a == 1) m1 |= 8; else if (a == 2) m2 |= 8;
        if (b == 1) m1 |= 4; else if (b == 2) m2 |= 4;
        if (c == 1) m1 |= 2; else if (c == 2) m2 |= 2;
        if (d == 1) m1 |= 1; else if (d == 2) m2 |= 1;

        const int bitpos = 3 - w;
        float sum = 0.f;
#pragma unroll
        for (int xo = 0; xo < 2; xo++) {
            const int x = part * 2 + xo;
            const int y = x ^ m2;
            const float sgn1 = (__popc(x & m1) & 1) ? -1.f : 1.f;
            float acc = 0.f;
#pragma unroll
            for (int j = 0; j < 16; j++) {
                const float sgn2 = ((j >> bitpos) & 1) ? -1.f : 1.f;
                acc += sgn2 * (shWre[j][x] * shWre[j][y] + shWim[j][x] * shWim[j][y]);
            }
            sum += sgn1 * acc;
        }
        sPart[coef][part] = sum;
    }
    __syncthreads();

    if (tid < 24) {
        float s = 0.f;
#pragma unroll
        for (int p = 0; p < 8; p++) s += sPart[tid][p];
        sP[tid] = s * 0.0625f;
    }
    __syncthreads();

    // ---- Phase 3: streaming evaluation ----
    float P[24];
#pragma unroll
    for (int k = 0; k < 24; k++) P[k] = sP[k];

    const int stride = gridDim.x * blockDim.x;
    for (int i = blockIdx.x * blockDim.x + tid; i < n; i += stride) {
        const float4 xv = x4[i];
        float c0, s0, c1, s1, c2, s2, c3, s3;
        __sincosf(xv.x, &s0, &c0);
        __sincosf(xv.y, &s1, &c1);
        __sincosf(xv.z, &s2, &c2);
        __sincosf(xv.w, &s3, &c3);

        // out0: wires 0,1,3
        float a1 = fmaf(P[1], s3, P[0] * c3);
        float a2 = fmaf(P[3], s3, P[2] * c3);
        float a3 = fmaf(P[5], s3, P[4] * c3);
        float a4 = fmaf(P[7], s3, P[6] * c3);
        float u1 = fmaf(a2, s1, a1 * c1);
        float u2 = fmaf(a4, s1, a3 * c1);
        const float o0 = fmaf(u2, s0, u1 * c0);

        // out1: wires 0,2,3
        float b1 = fmaf(P[9],  s3, P[8]  * c3);
        float b2 = fmaf(P[11], s3, P[10] * c3);
        float b3 = fmaf(P[13], s3, P[12] * c3);
        float b4 = fmaf(P[15], s3, P[14] * c3);
        float v1 = fmaf(b2, s2, b1 * c2);
        float v2 = fmaf(b4, s2, b3 * c2);
        const float o1 = fmaf(v2, s0, v1 * c0);

        // out2: wires 1,3
        float d1 = fmaf(P[17], s3, P[16] * c3);
        float d2 = fmaf(P[19], s3, P[18] * c3);
        const float o2 = fmaf(d2, s1, d1 * c1);

        // out3: wires 0,2
        float e1 = fmaf(P[21], s2, P[20] * c2);
        float e2 = fmaf(P[23], s2, P[22] * c2);
        const float o3 = fmaf(e2, s0, e1 * c0);

        out4[i] = make_float4(o0, o1, o2, o3);
    }
}

extern "C" void kernel_launch(void* const* d_in, const int* in_sizes, int n_in,
                              void* d_out, int out_size) {
    const float* x = (const float*)d_in[0];        // [B, 4] float32
    const float* weights = (const float*)d_in[1];  // [2, 4] float32
    float* out = (float*)d_out;                    // [B, 4] float32

    const int n = in_sizes[0] / 4;

    // 6 blocks/SM * 148 SMs = one full wave; grid-stride covers the rest.
    int grid = 888;
    const int maxGrid = (n + 255) / 256;
    if (grid > maxGrid) grid = maxGrid;

    qenc_fused_kernel<<<grid, 256>>>(weights, (const float4*)x, (float4*)out, n);
}

// round 10
// speedup vs baseline: 3.4200x; 1.0200x over previous
#include <cuda_runtime.h>

// 24 sparse multilinear coefficients (Pauli-propagation sparsity, validated
// R6/R8/R9):
//  [0..7]  out0(x0,x1,x3), [8..15] out1(x0,x2,x3),
//  [16..19] out2(x1,x3),   [20..23] out3(x0,x2)
__device__ __align__(16) float g_P[24];

// ---------------------------------------------------------------------------
// Prep kernel (1 block, 256 threads, runs once):
// Phase 1: shuffle-based circuit simulation — one amplitude per thread,
//   col = tid>>4, j = tid&15 (low 4 lane bits). RX = shfl_xor butterfly,
//   CNOT = lane permutation. Embedding phase (-i)^popcount(col) folded.
// Phase 2: 24 coefficients x 8 partials (2 x-terms each), reduce.
// ---------------------------------------------------------------------------
__global__ void prep_kernel(const float* __restrict__ weights) {
    __shared__ float shWre[16][16];   // [j][col]
    __shared__ float shWim[16][16];
    __shared__ float sPart[24][8];
    const int tid = threadIdx.x;
    const unsigned FULL = 0xffffffffu;

    // ---- Phase 1 ----
    {
        const int col = tid >> 4;
        const int j   = tid & 15;

        float re = (j == col) ? 1.f : 0.f;
        float im = 0.f;

#pragma unroll
        for (int l = 0; l < 2; l++) {
#pragma unroll
            for (int w = 0; w < 4; w++) {
                const float th = weights[l * 4 + w] * 0.5f;
                float c, s;
                __sincosf(th, &s, &c);
                const int bit = 8 >> w;
                const float pre = __shfl_xor_sync(FULL, re, bit);
                const float pim = __shfl_xor_sync(FULL, im, bit);
                const float nre = fmaf(c, re,  s * pim);
                const float nim = fmaf(c, im, -s * pre);
                re = nre; im = nim;
            }
#pragma unroll
            for (int w = 0; w < 4; w++) {
                const int cb = 8 >> w;
                const int tb = 8 >> ((w + 1) & 3);
                const int srcj = (j & cb) ? (j ^ tb) : j;
                const int srclane = (tid & 16) | srcj;
                re = __shfl_sync(FULL, re, srclane);
                im = __shfl_sync(FULL, im, srclane);
            }
        }

        const int pc = __popc(col) & 3;
        float wre, wim;
        if (pc == 0)      { wre = re;   wim = im;  }
        else if (pc == 1) { wre = im;   wim = -re; }
        else if (pc == 2) { wre = -re;  wim = -im; }
        else              { wre = -im;  wim = re;  }
        shWre[j][col] = wre;
        shWim[j][col] = wim;
    }
    __syncthreads();

    // ---- Phase 2 ----
    if (tid < 192) {
        const int coef = tid >> 3;
        const int part = tid & 7;

        int w, a, b, c, d;
        if (coef < 8)       { w = 0; a = (coef >> 2) + 1; b = ((coef >> 1) & 1) + 1; c = 0; d = (coef & 1) + 1; }
        else if (coef < 16) { int r = coef - 8;  w = 1; a = (r >> 2) + 1; b = 0; c = ((r >> 1) & 1) + 1; d = (r & 1) + 1; }
        else if (coef < 20) { int r = coef - 16; w = 2; a = 0; b = (r >> 1) + 1; c = 0; d = (r & 1) + 1; }
        else                { int r = coef - 20; w = 3; a = (r >> 1) + 1; b = 0; c = (r & 1) + 1; d = 0; }

        int m1 = 0, m2 = 0;
        if (a == 1) m1 |= 8; else if (a == 2) m2 |= 8;
        if (b == 1) m1 |= 4; else if (b == 2) m2 |= 4;
        if (c == 1) m1 |= 2; else if (c == 2) m2 |= 2;
        if (d == 1) m1 |= 1; else if (d == 2) m2 |= 1;

        const int bitpos = 3 - w;
        float sum = 0.f;
#pragma unroll
        for (int xo = 0; xo < 2; xo++) {
            const int x = part * 2 + xo;
            const int y = x ^ m2;
            const float sgn1 = (__popc(x & m1) & 1) ? -1.f : 1.f;
            float acc = 0.f;
#pragma unroll
            for (int j = 0; j < 16; j++) {
                const float sgn2 = ((j >> bitpos) & 1) ? -1.f : 1.f;
                acc += sgn2 * (shWre[j][x] * shWre[j][y] + shWim[j][x] * shWim[j][y]);
            }
            sum += sgn1 * acc;
        }
        sPart[coef][part] = sum;
    }
    __syncthreads();

    if (tid < 24) {
        float s = 0.f;
#pragma unroll
        for (int p = 0; p < 8; p++) s += sPart[tid][p];
        g_P[tid] = s * 0.0625f;
    }
}

// ---------------------------------------------------------------------------
// Main kernel: one sample per thread (R6-validated fastest config).
// P loaded once per thread via 6 uniform LDG.128 (L1 broadcast).
// ---------------------------------------------------------------------------
__global__ __launch_bounds__(256) void qenc_main_kernel(
    const float4* __restrict__ x4, float4* __restrict__ out4, int n)
{
    const int i = blockIdx.x * 256 + threadIdx.x;
    if (i >= n) return;

    float P[24];
    {
        const float4* Pg = (const float4*)g_P;
#pragma unroll
        for (int k = 0; k < 6; k++) {
            const float4 v = __ldg(&Pg[k]);
            P[4 * k + 0] = v.x; P[4 * k + 1] = v.y;
            P[4 * k + 2] = v.z; P[4 * k + 3] = v.w;
        }
    }

    const float4 xv = x4[i];
    float c0, s0, c1, s1, c2, s2, c3, s3;
    __sincosf(xv.x, &s0, &c0);
    __sincosf(xv.y, &s1, &c1);
    __sincosf(xv.z, &s2, &c2);
    __sincosf(xv.w, &s3, &c3);

    // out0: wires 0,1,3
    float a1 = fmaf(P[1], s3, P[0] * c3);
    float a2 = fmaf(P[3], s3, P[2] * c3);
    float a3 = fmaf(P[5], s3, P[4] * c3);
    float a4 = fmaf(P[7], s3, P[6] * c3);
    float u1 = fmaf(a2, s1, a1 * c1);
    float u2 = fmaf(a4, s1, a3 * c1);
    const float o0 = fmaf(u2, s0, u1 * c0);

    // out1: wires 0,2,3
    float b1 = fmaf(P[9],  s3, P[8]  * c3);
    float b2 = fmaf(P[11], s3, P[10] * c3);
    float b3 = fmaf(P[13], s3, P[12] * c3);
    float b4 = fmaf(P[15], s3, P[14] * c3);
    float v1 = fmaf(b2, s2, b1 * c2);
    float v2 = fmaf(b4, s2, b3 * c2);
    const float o1 = fmaf(v2, s0, v1 * c0);

    // out2: wires 1,3
    float d1 = fmaf(P[17], s3, P[16] * c3);
    float d2 = fmaf(P[19], s3, P[18] * c3);
    const float o2 = fmaf(d2, s1, d1 * c1);

    // out3: wires 0,2
    float e1 = fmaf(P[21], s2, P[20] * c2);
    float e2 = fmaf(P[23], s2, P[22] * c2);
    const float o3 = fmaf(e2, s0, e1 * c0);

    out4[i] = make_float4(o0, o1, o2, o3);
}

extern "C" void kernel_launch(void* const* d_in, const int* in_sizes, int n_in,
                              void* d_out, int out_size) {
    const float* x = (const float*)d_in[0];        // [B, 4] float32
    const float* weights = (const float*)d_in[1];  // [2, 4] float32
    float* out = (float*)d_out;                    // [B, 4] float32

    const int n = in_sizes[0] / 4;

    prep_kernel<<<1, 256>>>(weights);
    qenc_main_kernel<<<(n + 255) / 256, 256>>>(
        (const float4*)x, (float4*)out, n);
}